// round 1
// baseline (speedup 1.0000x reference)
#include <cuda_runtime.h>

// Problem constants
#define NH   16
#define HD   64
#define NN   64        // spatial positions H*W
#define CC   1024
#define BB   1024
#define PAD  68        // padded row stride (floats) for 64-wide smem tiles

// Scratch (device globals: allocation-free rule)
__device__ float g_attnout[(size_t)BB * CC * NN];   // 268 MB
__device__ float g_proj[(size_t)BB * CC * NN];      // 268 MB
__device__ float g_stats[2 * BB];

typedef unsigned long long u64t;

__device__ __forceinline__ u64t pk2(float a, float b) {
    u64t r; asm("mov.b64 %0, {%1,%2};" : "=l"(r) : "f"(a), "f"(b)); return r;
}
__device__ __forceinline__ u64t ffma2(u64t a, u64t b, u64t c) {
    u64t d; asm("fma.rn.f32x2 %0, %1, %2, %3;" : "=l"(d) : "l"(a), "l"(b), "l"(c)); return d;
}
__device__ __forceinline__ float2 upk2(u64t v) {
    float lo, hi; asm("mov.b64 {%0,%1}, %2;" : "=f"(lo), "=f"(hi) : "l"(v));
    float2 f; f.x = lo; f.y = hi; return f;
}

// ---------------------------------------------------------------------------
// Kernel 1: per-(b,head) fused QKV GEMM + l2norm(spatial) + softmax attention.
// Grid: BB*NH blocks, 256 threads. Dynamic smem ~70KB.
// Writes attention output (pre-projection) to g_attnout in [b][c][n] layout.
// ---------------------------------------------------------------------------
__global__ void __launch_bounds__(256) qkv_attn_kernel(
    const float* __restrict__ x,
    const float* __restrict__ Wq, const float* __restrict__ bq,
    const float* __restrict__ Wk, const float* __restrict__ bk,
    const float* __restrict__ Wv, const float* __restrict__ bv,
    const float* __restrict__ temp_p)
{
    extern __shared__ float sm[];
    float* qs  = sm;                 // [64][PAD]  q tile, layout [d][n]
    float* ks  = sm + 64 * PAD;      // [64][PAD]  k tile, layout [d][n]
    float* vsT = sm + 2 * 64 * PAD;  // [64][PAD]  v tile TRANSPOSED, [n][d]
    float* At  = sm + 3 * 64 * PAD;  // [64][PAD]  attn TRANSPOSED, [m][n]
    float* wt  = At;                 // alias: GEMM W tile [16][PAD] (k-major)
    float* xt  = At + 16 * PAD;      // alias: GEMM X tile [16][PAD]
    float* cd  = sm + 4 * 64 * PAD;  // [64] combined q-row scale
    float* knv = cd + 64;            // [64] k-row inv-norm

    const int t  = threadIdx.x;
    const int tx = t & 15, ty = t >> 4;
    const int b  = blockIdx.x >> 4;
    const int h  = blockIdx.x & 15;
    const float* xb = x + (size_t)b * (CC * NN);

    // tile-load thread mapping
    const int lrow = t >> 2;         // 0..63 : W output row
    const int lk4  = (t & 3) << 2;   // 0,4,8,12 : W k offset
    const int xr   = t >> 4;         // 0..15 : X k row
    const int xc4  = (t & 15) << 2;  // X n offset

    const float* Wmat[3] = {Wq, Wk, Wv};
    const float* Bvec[3] = {bq, bk, bv};

    for (int phase = 0; phase < 3; ++phase) {
        const float* W = Wmat[phase] + (size_t)h * 64 * CC;
        u64t acc[4][2];
        #pragma unroll
        for (int i = 0; i < 4; ++i) { acc[i][0] = 0ull; acc[i][1] = 0ull; }

        for (int k0 = 0; k0 < CC; k0 += 16) {
            float4 wv4 = *(const float4*)(W + (size_t)lrow * CC + k0 + lk4);
            float4 xv4 = *(const float4*)(xb + (size_t)(k0 + xr) * NN + xc4);
            __syncthreads();   // previous compute done before overwrite
            wt[(lk4 + 0) * PAD + lrow] = wv4.x;
            wt[(lk4 + 1) * PAD + lrow] = wv4.y;
            wt[(lk4 + 2) * PAD + lrow] = wv4.z;
            wt[(lk4 + 3) * PAD + lrow] = wv4.w;
            *(float4*)(xt + xr * PAD + xc4) = xv4;
            __syncthreads();
            #pragma unroll
            for (int kk = 0; kk < 16; ++kk) {
                float4 av = *(const float4*)(wt + kk * PAD + (ty << 2));
                ulonglong2 bv2 = *(const ulonglong2*)(xt + kk * PAD + (tx << 2));
                u64t a0 = pk2(av.x, av.x), a1 = pk2(av.y, av.y);
                u64t a2 = pk2(av.z, av.z), a3 = pk2(av.w, av.w);
                acc[0][0] = ffma2(a0, bv2.x, acc[0][0]); acc[0][1] = ffma2(a0, bv2.y, acc[0][1]);
                acc[1][0] = ffma2(a1, bv2.x, acc[1][0]); acc[1][1] = ffma2(a1, bv2.y, acc[1][1]);
                acc[2][0] = ffma2(a2, bv2.x, acc[2][0]); acc[2][1] = ffma2(a2, bv2.y, acc[2][1]);
                acc[3][0] = ffma2(a3, bv2.x, acc[3][0]); acc[3][1] = ffma2(a3, bv2.y, acc[3][1]);
            }
        }
        // epilogue: bias + store to q/k/vT tiles
        const float* bias = Bvec[phase] + h * 64;
        #pragma unroll
        for (int i = 0; i < 4; ++i) {
            int d = (ty << 2) + i;
            float bi = bias[d];
            float2 v01 = upk2(acc[i][0]);
            float2 v23 = upk2(acc[i][1]);
            float v0 = v01.x + bi, v1 = v01.y + bi, v2 = v23.x + bi, v3 = v23.y + bi;
            if (phase == 0) {
                float* r = qs + d * PAD + (tx << 2);
                r[0] = v0; r[1] = v1; r[2] = v2; r[3] = v3;
            } else if (phase == 1) {
                float* r = ks + d * PAD + (tx << 2);
                r[0] = v0; r[1] = v1; r[2] = v2; r[3] = v3;
            } else {
                int n0 = tx << 2;
                vsT[(n0 + 0) * PAD + d] = v0;
                vsT[(n0 + 1) * PAD + d] = v1;
                vsT[(n0 + 2) * PAD + d] = v2;
                vsT[(n0 + 3) * PAD + d] = v3;
            }
        }
    }
    __syncthreads();

    // l2 norms over spatial axis (per d row) for q and k
    float tinv = 1.0f / (temp_p[0] + 1e-6f);
    if (t < 64) {
        float s = 0.f;
        #pragma unroll 8
        for (int n = 0; n < 64; ++n) { float v = qs[t * PAD + n]; s += v * v; }
        cd[t] = 1.0f / fmaxf(sqrtf(s), 1e-12f);
    } else if (t < 128) {
        int r = t - 64;
        float s = 0.f;
        #pragma unroll 8
        for (int n = 0; n < 64; ++n) { float v = ks[r * PAD + n]; s += v * v; }
        knv[r] = 1.0f / fmaxf(sqrtf(s), 1e-12f);
    }
    __syncthreads();
    // fold qnorm*knorm*(1/(T+eps)) into q rows
    for (int i = t; i < 64 * 64; i += 256) {
        int d = i >> 6, n = i & 63;
        qs[d * PAD + n] *= cd[d] * knv[d] * tinv;
    }
    __syncthreads();

    // S[n][m] = sum_d qhat[d][n] * khat[d][m]
    u64t sa[4][2];
    #pragma unroll
    for (int i = 0; i < 4; ++i) { sa[i][0] = 0ull; sa[i][1] = 0ull; }
    #pragma unroll 4
    for (int d = 0; d < 64; ++d) {
        float4 av = *(const float4*)(qs + d * PAD + (ty << 2));   // n frag
        ulonglong2 bv2 = *(const ulonglong2*)(ks + d * PAD + (tx << 2)); // m frag
        u64t a0 = pk2(av.x, av.x), a1 = pk2(av.y, av.y);
        u64t a2 = pk2(av.z, av.z), a3 = pk2(av.w, av.w);
        sa[0][0] = ffma2(a0, bv2.x, sa[0][0]); sa[0][1] = ffma2(a0, bv2.y, sa[0][1]);
        sa[1][0] = ffma2(a1, bv2.x, sa[1][0]); sa[1][1] = ffma2(a1, bv2.y, sa[1][1]);
        sa[2][0] = ffma2(a2, bv2.x, sa[2][0]); sa[2][1] = ffma2(a2, bv2.y, sa[2][1]);
        sa[3][0] = ffma2(a3, bv2.x, sa[3][0]); sa[3][1] = ffma2(a3, bv2.y, sa[3][1]);
    }

    // softmax over m (16 threads of same ty hold one n-row; lanes are a 16-group)
    #pragma unroll
    for (int i = 0; i < 4; ++i) {
        float2 s01 = upk2(sa[i][0]);
        float2 s23 = upk2(sa[i][1]);
        float s0 = s01.x, s1 = s01.y, s2 = s23.x, s3 = s23.y;
        float mx = fmaxf(fmaxf(s0, s1), fmaxf(s2, s3));
        #pragma unroll
        for (int o = 8; o; o >>= 1) mx = fmaxf(mx, __shfl_xor_sync(0xffffffffu, mx, o));
        float e0 = __expf(s0 - mx), e1 = __expf(s1 - mx);
        float e2 = __expf(s2 - mx), e3 = __expf(s3 - mx);
        float sum = e0 + e1 + e2 + e3;
        #pragma unroll
        for (int o = 8; o; o >>= 1) sum += __shfl_xor_sync(0xffffffffu, sum, o);
        float rinv = 1.0f / sum;
        int n = (ty << 2) + i, m0 = tx << 2;
        At[(m0 + 0) * PAD + n] = e0 * rinv;
        At[(m0 + 1) * PAD + n] = e1 * rinv;
        At[(m0 + 2) * PAD + n] = e2 * rinv;
        At[(m0 + 3) * PAD + n] = e3 * rinv;
    }
    __syncthreads();

    // O[d][n] = sum_m A[n][m] * v[d][m]  (read At[m][n], vsT[m][d])
    u64t oa[4][2];
    #pragma unroll
    for (int i = 0; i < 4; ++i) { oa[i][0] = 0ull; oa[i][1] = 0ull; }
    #pragma unroll 4
    for (int m = 0; m < 64; ++m) {
        float4 av = *(const float4*)(At + m * PAD + (ty << 2));        // n frag
        ulonglong2 bv2 = *(const ulonglong2*)(vsT + m * PAD + (tx << 2)); // d frag
        u64t a0 = pk2(av.x, av.x), a1 = pk2(av.y, av.y);
        u64t a2 = pk2(av.z, av.z), a3 = pk2(av.w, av.w);
        oa[0][0] = ffma2(a0, bv2.x, oa[0][0]); oa[0][1] = ffma2(a0, bv2.y, oa[0][1]);
        oa[1][0] = ffma2(a1, bv2.x, oa[1][0]); oa[1][1] = ffma2(a1, bv2.y, oa[1][1]);
        oa[2][0] = ffma2(a2, bv2.x, oa[2][0]); oa[2][1] = ffma2(a2, bv2.y, oa[2][1]);
        oa[3][0] = ffma2(a3, bv2.x, oa[3][0]); oa[3][1] = ffma2(a3, bv2.y, oa[3][1]);
    }
    // unpack: o_[i = n local][j = d local]
    float o_[4][4];
    #pragma unroll
    for (int i = 0; i < 4; ++i) {
        float2 v01 = upk2(oa[i][0]);
        float2 v23 = upk2(oa[i][1]);
        o_[i][0] = v01.x; o_[i][1] = v01.y; o_[i][2] = v23.x; o_[i][3] = v23.y;
    }
    float* outb = g_attnout + (size_t)b * (CC * NN) + (size_t)(h * 64) * NN;
    #pragma unroll
    for (int j = 0; j < 4; ++j) {
        int d = (tx << 2) + j;
        float4 w4 = make_float4(o_[0][j], o_[1][j], o_[2][j], o_[3][j]);
        *(float4*)(outb + d * NN + (ty << 2)) = w4;
    }
}

// ---------------------------------------------------------------------------
// Kernel 2: projection GEMM  g_proj[b][c][n] = Wp @ g_attnout[b] + bp
// Grid: (16 row-tiles, BB batches), 256 threads.
// ---------------------------------------------------------------------------
__global__ void __launch_bounds__(256) proj_kernel(
    const float* __restrict__ Wp, const float* __restrict__ bp)
{
    __shared__ float wt[16 * PAD];
    __shared__ float xt[16 * PAD];
    const int t  = threadIdx.x;
    const int tx = t & 15, ty = t >> 4;
    const int tile = blockIdx.x;      // 0..15
    const int b    = blockIdx.y;
    const float* inb = g_attnout + (size_t)b * (CC * NN);
    const float* W   = Wp + (size_t)tile * 64 * CC;

    const int lrow = t >> 2;
    const int lk4  = (t & 3) << 2;
    const int xr   = t >> 4;
    const int xc4  = (t & 15) << 2;

    u64t acc[4][2];
    #pragma unroll
    for (int i = 0; i < 4; ++i) { acc[i][0] = 0ull; acc[i][1] = 0ull; }

    for (int k0 = 0; k0 < CC; k0 += 16) {
        float4 wv4 = *(const float4*)(W + (size_t)lrow * CC + k0 + lk4);
        float4 xv4 = *(const float4*)(inb + (size_t)(k0 + xr) * NN + xc4);
        __syncthreads();
        wt[(lk4 + 0) * PAD + lrow] = wv4.x;
        wt[(lk4 + 1) * PAD + lrow] = wv4.y;
        wt[(lk4 + 2) * PAD + lrow] = wv4.z;
        wt[(lk4 + 3) * PAD + lrow] = wv4.w;
        *(float4*)(xt + xr * PAD + xc4) = xv4;
        __syncthreads();
        #pragma unroll
        for (int kk = 0; kk < 16; ++kk) {
            float4 av = *(const float4*)(wt + kk * PAD + (ty << 2));
            ulonglong2 bv2 = *(const ulonglong2*)(xt + kk * PAD + (tx << 2));
            u64t a0 = pk2(av.x, av.x), a1 = pk2(av.y, av.y);
            u64t a2 = pk2(av.z, av.z), a3 = pk2(av.w, av.w);
            acc[0][0] = ffma2(a0, bv2.x, acc[0][0]); acc[0][1] = ffma2(a0, bv2.y, acc[0][1]);
            acc[1][0] = ffma2(a1, bv2.x, acc[1][0]); acc[1][1] = ffma2(a1, bv2.y, acc[1][1]);
            acc[2][0] = ffma2(a2, bv2.x, acc[2][0]); acc[2][1] = ffma2(a2, bv2.y, acc[2][1]);
            acc[3][0] = ffma2(a3, bv2.x, acc[3][0]); acc[3][1] = ffma2(a3, bv2.y, acc[3][1]);
        }
    }
    float* outb = g_proj + (size_t)b * (CC * NN);
    #pragma unroll
    for (int i = 0; i < 4; ++i) {
        int c = tile * 64 + (ty << 2) + i;
        float bi = bp[c];
        float2 v01 = upk2(acc[i][0]);
        float2 v23 = upk2(acc[i][1]);
        float4 w4 = make_float4(v01.x + bi, v01.y + bi, v23.x + bi, v23.y + bi);
        *(float4*)(outb + (size_t)c * NN + (tx << 2)) = w4;
    }
}

// ---------------------------------------------------------------------------
// Kernel 3: per-batch mean/var of residual r = g*proj + (1-g)*x
// ---------------------------------------------------------------------------
__global__ void __launch_bounds__(256) stats_kernel(
    const float* __restrict__ x, const float* __restrict__ gamma_p)
{
    __shared__ float r1[8], r2[8];
    const int b = blockIdx.x, t = threadIdx.x;
    const float g = gamma_p[0], og = 1.0f - g;
    const float* pb = g_proj + (size_t)b * 65536;
    const float* xb = x + (size_t)b * 65536;
    float s1 = 0.f, s2 = 0.f;
    for (int i = t * 4; i < 65536; i += 1024) {
        float4 p  = *(const float4*)(pb + i);
        float4 xx = *(const float4*)(xb + i);
        float a;
        a = g * p.x + og * xx.x; s1 += a; s2 += a * a;
        a = g * p.y + og * xx.y; s1 += a; s2 += a * a;
        a = g * p.z + og * xx.z; s1 += a; s2 += a * a;
        a = g * p.w + og * xx.w; s1 += a; s2 += a * a;
    }
    #pragma unroll
    for (int o = 16; o; o >>= 1) {
        s1 += __shfl_xor_sync(0xffffffffu, s1, o);
        s2 += __shfl_xor_sync(0xffffffffu, s2, o);
    }
    if ((t & 31) == 0) { r1[t >> 5] = s1; r2[t >> 5] = s2; }
    __syncthreads();
    if (t < 8) {
        s1 = r1[t]; s2 = r2[t];
        #pragma unroll
        for (int o = 4; o; o >>= 1) {
            s1 += __shfl_xor_sync(0x000000ffu, s1, o);
            s2 += __shfl_xor_sync(0x000000ffu, s2, o);
        }
        if (t == 0) {
            float mu  = s1 * (1.0f / 65536.0f);
            float var = s2 * (1.0f / 65536.0f) - mu * mu;
            g_stats[2 * b]     = mu;
            g_stats[2 * b + 1] = rsqrtf(var + 1e-5f);
        }
    }
}

// ---------------------------------------------------------------------------
// Kernel 4: y = (r - mu)*rstd*ln_w + ln_b
// ---------------------------------------------------------------------------
__global__ void __launch_bounds__(256) final_kernel(
    const float* __restrict__ x, const float* __restrict__ gamma_p,
    const float* __restrict__ lnw, const float* __restrict__ lnb,
    float* __restrict__ y)
{
    size_t i4 = (size_t)blockIdx.x * 256 + threadIdx.x;   // float4 index
    int b   = (int)(i4 >> 14);               // 16384 float4 per batch
    int rem = (int)(i4 & 16383);
    size_t base = ((size_t)b << 16) + ((size_t)rem << 2);
    float4 p  = *(const float4*)(g_proj + base);
    float4 xx = *(const float4*)(x + base);
    float4 w  = *(const float4*)(lnw + ((size_t)rem << 2));
    float4 lb = *(const float4*)(lnb + ((size_t)rem << 2));
    float g = gamma_p[0], og = 1.0f - g;
    float mu = g_stats[2 * b], rs = g_stats[2 * b + 1];
    float4 o;
    o.x = (g * p.x + og * xx.x - mu) * rs * w.x + lb.x;
    o.y = (g * p.y + og * xx.y - mu) * rs * w.y + lb.y;
    o.z = (g * p.z + og * xx.z - mu) * rs * w.z + lb.z;
    o.w = (g * p.w + og * xx.w - mu) * rs * w.w + lb.w;
    *(float4*)(y + base) = o;
}

// ---------------------------------------------------------------------------
extern "C" void kernel_launch(void* const* d_in, const int* in_sizes, int n_in,
                              void* d_out, int out_size)
{
    const float* x     = (const float*)d_in[0];
    const float* Wq    = (const float*)d_in[1];
    const float* bq    = (const float*)d_in[2];
    const float* Wk    = (const float*)d_in[3];
    const float* bk    = (const float*)d_in[4];
    const float* Wv    = (const float*)d_in[5];
    const float* bv    = (const float*)d_in[6];
    const float* Wp    = (const float*)d_in[7];
    const float* bp    = (const float*)d_in[8];
    const float* gamma = (const float*)d_in[9];
    const float* temp  = (const float*)d_in[10];
    const float* lnw   = (const float*)d_in[11];
    const float* lnb   = (const float*)d_in[12];
    float* y = (float*)d_out;

    const int smem_bytes = (4 * 64 * PAD + 128) * (int)sizeof(float);  // ~70 KB
    cudaFuncSetAttribute(qkv_attn_kernel,
                         cudaFuncAttributeMaxDynamicSharedMemorySize, smem_bytes);

    qkv_attn_kernel<<<BB * NH, 256, smem_bytes>>>(x, Wq, bq, Wk, bk, Wv, bv, temp);
    proj_kernel<<<dim3(16, BB), 256>>>(Wp, bp);
    stats_kernel<<<BB, 256>>>(x, gamma);
    final_kernel<<<65536, 256>>>(x, gamma, lnw, lnb, y);
}

// round 3
// speedup vs baseline: 2.8205x; 2.8205x over previous
#include <cuda_runtime.h>
#include <cuda_bf16.h>

#define NH   16
#define NN   64
#define CC   1024
#define BB   1024
#define PAD  68

typedef unsigned int u32;
typedef unsigned long long u64;
typedef unsigned short u16;

#define QKVSZ 67108864ull          // 1024*64*1024 elems

// Scratch (allocation-free rule: device globals)
__device__ u16   g_xhi [(size_t)BB * NN * CC];    // x transposed, bf16 hi [pixel][ch]
__device__ u16   g_xlo [(size_t)BB * NN * CC];
__device__ u16   g_whi [(size_t)4096 * CC];       // Wq,Wk,Wv,Wp fused rows
__device__ u16   g_wlo [(size_t)4096 * CC];
__device__ float g_qkv [3ull * QKVSZ];            // q,k,v fp32 [pixel][ch]
__device__ u16   g_ohi [(size_t)BB * NN * CC];    // attn out bf16 hi [pixel][ch]
__device__ u16   g_olo [(size_t)BB * NN * CC];
__device__ float g_proj[(size_t)BB * CC * NN];    // proj out [b][c][n]
__device__ float g_stats[2 * BB];

// ---------------------------------------------------------------------------
// helpers
// ---------------------------------------------------------------------------
__device__ __forceinline__ u32 smem_u32(const void* p) {
    u32 a;
    asm("{ .reg .u64 t; cvta.to.shared.u64 t, %1; cvt.u32.u64 %0, t; }" : "=r"(a) : "l"(p));
    return a;
}
__device__ __forceinline__ void cpa16(u32 dst, const void* src) {
    asm volatile("cp.async.cg.shared.global [%0], [%1], 16;" :: "r"(dst), "l"(src));
}
#define CP_COMMIT() asm volatile("cp.async.commit_group;" ::: "memory")
#define CP_WAIT2()  asm volatile("cp.async.wait_group 2;" ::: "memory")

__device__ __forceinline__ u32 lds32(u32 a) {
    u32 v; asm volatile("ld.shared.b32 %0, [%1];" : "=r"(v) : "r"(a)); return v;
}
__device__ __forceinline__ void mma16816(float* c, const u32* a, const u32* b) {
    asm volatile("mma.sync.aligned.m16n8k16.row.col.f32.bf16.bf16.f32 "
        "{%0,%1,%2,%3}, {%4,%5,%6,%7}, {%8,%9}, {%0,%1,%2,%3};"
        : "+f"(c[0]), "+f"(c[1]), "+f"(c[2]), "+f"(c[3])
        : "r"(a[0]), "r"(a[1]), "r"(a[2]), "r"(a[3]), "r"(b[0]), "r"(b[1]));
}
// swizzled smem byte address: rows of 64B (4 chunks), chunk ^= (row>>1)&3
__device__ __forceinline__ u32 sw_addr(u32 base, int row, int kbyte) {
    int chunk = kbyte >> 4, in = kbyte & 15;
    return base + row * 64 + ((chunk ^ ((row >> 1) & 3)) << 4) + in;
}
__device__ __forceinline__ u16 bf16hi_bits(float f) {
    return (u16)(__float_as_uint(f) >> 16);
}
__device__ __forceinline__ u16 bf16lo_bits(float f) {
    float hi = __uint_as_float(__float_as_uint(f) & 0xFFFF0000u);
    __nv_bfloat16 h = __float2bfloat16(f - hi);
    return *reinterpret_cast<u16*>(&h);
}

// FFMA2 helpers (attention)
typedef unsigned long long u64t;
__device__ __forceinline__ u64t pk2(float a, float b) {
    u64t r; asm("mov.b64 %0, {%1,%2};" : "=l"(r) : "f"(a), "f"(b)); return r;
}
__device__ __forceinline__ u64t ffma2(u64t a, u64t b, u64t c) {
    u64t d; asm("fma.rn.f32x2 %0, %1, %2, %3;" : "=l"(d) : "l"(a), "l"(b), "l"(c)); return d;
}
__device__ __forceinline__ float2 upk2(u64t v) {
    float lo, hi; asm("mov.b64 {%0,%1}, %2;" : "=f"(lo), "=f"(hi) : "l"(v));
    float2 f; f.x = lo; f.y = hi; return f;
}

// GEMM smem: 4 stages x 32KB (Ah 8K | Al 8K | Bh 8K | Bl 8K per stage)
#define STAGE_BYTES 32768
#define SM_GEMM     (4 * STAGE_BYTES)

// ---------------------------------------------------------------------------
// prep_w: 4 weight matrices -> fused hi/lo bf16 [4096][1024]
// grid 4096, 256 thr, 4 elems/thread
// ---------------------------------------------------------------------------
__global__ void __launch_bounds__(256) prep_w_kernel(
    const float* __restrict__ Wq, const float* __restrict__ Wk,
    const float* __restrict__ Wv, const float* __restrict__ Wp)
{
    int blk = blockIdx.x;
    int mat = blk >> 10;
    const float* src = (mat == 0) ? Wq : (mat == 1) ? Wk : (mat == 2) ? Wv : Wp;
    size_t idx = ((size_t)(blk & 1023) * 256 + threadIdx.x) * 4;
    float4 v = *(const float4*)(src + idx);
    size_t o = (size_t)mat * 1048576 + idx;
    ushort4 h, l;
    h.x = bf16hi_bits(v.x); h.y = bf16hi_bits(v.y);
    h.z = bf16hi_bits(v.z); h.w = bf16hi_bits(v.w);
    l.x = bf16lo_bits(v.x); l.y = bf16lo_bits(v.y);
    l.z = bf16lo_bits(v.z); l.w = bf16lo_bits(v.w);
    *(ushort4*)(g_whi + o) = h;
    *(ushort4*)(g_wlo + o) = l;
}

// ---------------------------------------------------------------------------
// prep_x: x[b][c][n] -> transposed hi/lo bf16 [pixel=b*64+n][c]
// ---------------------------------------------------------------------------
__global__ void __launch_bounds__(256) prep_x_kernel(const float* __restrict__ x) {
    __shared__ u16 hT[64][72];
    __shared__ u16 lT[64][72];
    const int b = blockIdx.x, t = threadIdx.x;
    const float* xb = x + (size_t)b * 65536;
    for (int ct = 0; ct < 16; ++ct) {
        #pragma unroll
        for (int i = 0; i < 16; ++i) {
            int idx = i * 256 + t, c = idx >> 6, n = idx & 63;
            float v = xb[(ct * 64 + c) * 64 + n];
            hT[n][c] = bf16hi_bits(v);
            lT[n][c] = bf16lo_bits(v);
        }
        __syncthreads();
        #pragma unroll
        for (int i = 0; i < 2; ++i) {
            int idx = i * 256 + t;
            int n = idx >> 3, c8 = (idx & 7) << 3;
            size_t o = (size_t)(b * 64 + n) * 1024 + ct * 64 + c8;
            *(uint4*)(g_xhi + o) = *(const uint4*)&hT[n][c8];
            *(uint4*)(g_xlo + o) = *(const uint4*)&lT[n][c8];
        }
        __syncthreads();
    }
}

// ---------------------------------------------------------------------------
// GEMM core: C[128 pix][128 ch] = A(hi+lo) x B(hi+lo)^T over K=1024.
// A,B bf16 [row][k] k-major, row stride 2048B. 8 warps, warp tile 64x32.
// ---------------------------------------------------------------------------
__device__ __forceinline__ void gemm_issue_stage(
    u32 sb, int s, int c,
    const char* gAh, const char* gAl, const char* gBh, const char* gBl)
{
    const int t = threadIdx.x;
    const char* gsrc[4] = {gAh, gAl, gBh, gBl};
    u32 stb = sb + s * STAGE_BYTES;
    #pragma unroll
    for (int arr = 0; arr < 4; ++arr) {
        #pragma unroll
        for (int r2 = 0; r2 < 2; ++r2) {
            int ch = t + r2 * 256;
            int row = ch >> 2, part = ch & 3;
            u32 dst = stb + arr * 8192 + row * 64 + ((part ^ ((row >> 1) & 3)) << 4);
            const char* src = gsrc[arr] + (size_t)row * 2048 + c * 64 + part * 16;
            cpa16(dst, src);
        }
    }
    CP_COMMIT();
}

__device__ __forceinline__ void gemm_compute_stage(u32 sb, int s, float acc[4][4][4],
                                                   int wm, int wn, int grp, int tig)
{
    u32 stb = sb + s * STAGE_BYTES;
    u32 pAh = stb, pAl = stb + 8192, pBh = stb + 16384, pBl = stb + 24576;
    #pragma unroll
    for (int ks = 0; ks < 2; ++ks) {
        int kb = ks * 32 + tig * 4;
        u32 A[4][4], B[4][2];
        // Ah frags
        #pragma unroll
        for (int i = 0; i < 4; ++i) {
            int r0 = wm + i * 16 + grp;
            A[i][0] = lds32(sw_addr(pAh, r0,     kb));
            A[i][1] = lds32(sw_addr(pAh, r0 + 8, kb));
            A[i][2] = lds32(sw_addr(pAh, r0,     kb + 16));
            A[i][3] = lds32(sw_addr(pAh, r0 + 8, kb + 16));
        }
        // Bh frags
        #pragma unroll
        for (int j = 0; j < 4; ++j) {
            int rn = wn + j * 8 + grp;
            B[j][0] = lds32(sw_addr(pBh, rn, kb));
            B[j][1] = lds32(sw_addr(pBh, rn, kb + 16));
        }
        #pragma unroll
        for (int i = 0; i < 4; ++i)
            #pragma unroll
            for (int j = 0; j < 4; ++j) mma16816(acc[i][j], A[i], B[j]);
        // Bl frags (Ah x Bl)
        #pragma unroll
        for (int j = 0; j < 4; ++j) {
            int rn = wn + j * 8 + grp;
            B[j][0] = lds32(sw_addr(pBl, rn, kb));
            B[j][1] = lds32(sw_addr(pBl, rn, kb + 16));
        }
        #pragma unroll
        for (int i = 0; i < 4; ++i)
            #pragma unroll
            for (int j = 0; j < 4; ++j) mma16816(acc[i][j], A[i], B[j]);
        // Al frags (Al x Bh)
        #pragma unroll
        for (int i = 0; i < 4; ++i) {
            int r0 = wm + i * 16 + grp;
            A[i][0] = lds32(sw_addr(pAl, r0,     kb));
            A[i][1] = lds32(sw_addr(pAl, r0 + 8, kb));
            A[i][2] = lds32(sw_addr(pAl, r0,     kb + 16));
            A[i][3] = lds32(sw_addr(pAl, r0 + 8, kb + 16));
        }
        #pragma unroll
        for (int j = 0; j < 4; ++j) {
            int rn = wn + j * 8 + grp;
            B[j][0] = lds32(sw_addr(pBh, rn, kb));
            B[j][1] = lds32(sw_addr(pBh, rn, kb + 16));
        }
        #pragma unroll
        for (int i = 0; i < 4; ++i)
            #pragma unroll
            for (int j = 0; j < 4; ++j) mma16816(acc[i][j], A[i], B[j]);
    }
}

#define GEMM_MAINLOOP(gAh, gAl, gBh, gBl, acc)                                  \
    do {                                                                        \
        gemm_issue_stage(sb, 0, 0, gAh, gAl, gBh, gBl);                         \
        gemm_issue_stage(sb, 1, 1, gAh, gAl, gBh, gBl);                         \
        gemm_issue_stage(sb, 2, 2, gAh, gAl, gBh, gBl);                         \
        for (int c = 0; c < 32; ++c) {                                          \
            CP_WAIT2();                                                         \
            __syncthreads();                                                    \
            gemm_compute_stage(sb, c & 3, acc, wm, wn, grp, tig);               \
            if (c + 3 < 32) gemm_issue_stage(sb, (c + 3) & 3, c + 3, gAh, gAl, gBh, gBl); \
            else CP_COMMIT();                                                   \
        }                                                                       \
    } while (0)

// ---------------------------------------------------------------------------
// QKV GEMM: grid (24 ntiles, 512 pixel-groups). out fp32 q/k/v [pixel][ch]+bias
// ---------------------------------------------------------------------------
__global__ void __launch_bounds__(256) qkv_gemm_kernel(
    const float* __restrict__ bq, const float* __restrict__ bk,
    const float* __restrict__ bv)
{
    extern __shared__ char smc[];
    const u32 sb = smem_u32(smc);
    const int t = threadIdx.x, wid = t >> 5, lane = t & 31;
    const int grp = lane >> 2, tig = lane & 3;
    const int wm = (wid & 1) << 6, wn = (wid >> 1) << 5;
    const int nt = blockIdx.x, mg = blockIdx.y;

    const char* gAh = (const char*)g_xhi + (size_t)mg * 128 * 2048;
    const char* gAl = (const char*)g_xlo + (size_t)mg * 128 * 2048;
    const char* gBh = (const char*)g_whi + (size_t)nt * 128 * 2048;
    const char* gBl = (const char*)g_wlo + (size_t)nt * 128 * 2048;

    float acc[4][4][4];
    #pragma unroll
    for (int i = 0; i < 4; ++i)
        #pragma unroll
        for (int j = 0; j < 4; ++j) { acc[i][j][0]=0.f; acc[i][j][1]=0.f; acc[i][j][2]=0.f; acc[i][j][3]=0.f; }

    GEMM_MAINLOOP(gAh, gAl, gBh, gBl, acc);

    const int sel = nt >> 3;
    const int cbase = (nt & 7) * 128;
    const float* bias = (sel == 0) ? bq : (sel == 1) ? bk : bv;
    float* out = g_qkv + (size_t)sel * QKVSZ;
    #pragma unroll
    for (int i = 0; i < 4; ++i) {
        int prow = mg * 128 + wm + i * 16 + grp;
        #pragma unroll
        for (int j = 0; j < 4; ++j) {
            int col = cbase + wn + j * 8 + tig * 2;
            float b0 = bias[col], b1 = bias[col + 1];
            float* o = out + (size_t)prow * 1024 + col;
            *(float2*)o = make_float2(acc[i][j][0] + b0, acc[i][j][1] + b1);
            *(float2*)(o + 8 * 1024) = make_float2(acc[i][j][2] + b0, acc[i][j][3] + b1);
        }
    }
}

// ---------------------------------------------------------------------------
// Proj GEMM: grid (8 ntiles, 512 pixel-groups). A = attn out (hi/lo).
// Epilogue: smem transpose -> g_proj [b][c][n] + bias.
// ---------------------------------------------------------------------------
__global__ void __launch_bounds__(256) proj_gemm_kernel(const float* __restrict__ bp)
{
    extern __shared__ char smc[];
    const u32 sb = smem_u32(smc);
    const int t = threadIdx.x, wid = t >> 5, lane = t & 31;
    const int grp = lane >> 2, tig = lane & 3;
    const int wm = (wid & 1) << 6, wn = (wid >> 1) << 5;
    const int nt = blockIdx.x, mg = blockIdx.y;

    const char* gAh = (const char*)g_ohi + (size_t)mg * 128 * 2048;
    const char* gAl = (const char*)g_olo + (size_t)mg * 128 * 2048;
    const char* gBh = (const char*)g_whi + (size_t)(3072 + nt * 128) * 2048;
    const char* gBl = (const char*)g_wlo + (size_t)(3072 + nt * 128) * 2048;

    float acc[4][4][4];
    #pragma unroll
    for (int i = 0; i < 4; ++i)
        #pragma unroll
        for (int j = 0; j < 4; ++j) { acc[i][j][0]=0.f; acc[i][j][1]=0.f; acc[i][j][2]=0.f; acc[i][j][3]=0.f; }

    GEMM_MAINLOOP(gAh, gAl, gBh, gBl, acc);

    // stash C tile [pm][cc] in smem (stages 0-2 region; stage 3 still in use is
    // untouched: 128*130*4 = 66560 < 98304)
    float* tile = (float*)smc;
    #pragma unroll
    for (int i = 0; i < 4; ++i) {
        int pm = wm + i * 16 + grp;
        #pragma unroll
        for (int j = 0; j < 4; ++j) {
            int cc = wn + j * 8 + tig * 2;
            *(float2*)&tile[pm * 130 + cc] = make_float2(acc[i][j][0], acc[i][j][1]);
            *(float2*)&tile[(pm + 8) * 130 + cc] = make_float2(acc[i][j][2], acc[i][j][3]);
        }
    }
    __syncthreads();
    #pragma unroll
    for (int it = 0; it < 16; ++it) {
        int idx = it * 256 + t;
        int cc = idx >> 5;
        int q = idx & 31, half = q >> 4, n4 = (q & 15) << 2;
        int ch = nt * 128 + cc;
        float bi = bp[ch];
        int pm0 = half * 64 + n4;
        float4 v;
        v.x = tile[(pm0 + 0) * 130 + cc] + bi;
        v.y = tile[(pm0 + 1) * 130 + cc] + bi;
        v.z = tile[(pm0 + 2) * 130 + cc] + bi;
        v.w = tile[(pm0 + 3) * 130 + cc] + bi;
        int b = mg * 2 + half;
        *(float4*)(g_proj + (size_t)b * 65536 + (size_t)ch * 64 + n4) = v;
    }
}

// ---------------------------------------------------------------------------
// Attention: per (b, head). Reads g_qkv fp32 [pixel][ch]; writes hi/lo bf16.
// ---------------------------------------------------------------------------
__global__ void __launch_bounds__(256) attn_kernel(const float* __restrict__ temp_p)
{
    extern __shared__ float sm[];
    float* qs  = sm;                 // [d][n]
    float* ks  = sm + 64 * PAD;
    float* vsT = sm + 2 * 64 * PAD;  // [n][d]
    float* At  = sm + 3 * 64 * PAD;  // [m][n]
    float* cd  = sm + 4 * 64 * PAD;
    float* knv = cd + 64;

    const int t  = threadIdx.x;
    const int tx = t & 15, ty = t >> 4;
    const int b  = blockIdx.x >> 4;
    const int h  = blockIdx.x & 15;

    const size_t base = (size_t)b * 65536 + h * 64;
    const float* qg = g_qkv + base;
    const float* kg = g_qkv + QKVSZ + base;
    const float* vg = g_qkv + 2 * QKVSZ + base;

    #pragma unroll
    for (int i = 0; i < 4; ++i) {
        int idx = i * 256 + t;
        int n = idx >> 4, d4 = (idx & 15) << 2;
        size_t off = (size_t)n * 1024 + d4;
        float4 qv = *(const float4*)(qg + off);
        qs[(d4 + 0) * PAD + n] = qv.x; qs[(d4 + 1) * PAD + n] = qv.y;
        qs[(d4 + 2) * PAD + n] = qv.z; qs[(d4 + 3) * PAD + n] = qv.w;
        float4 kv = *(const float4*)(kg + off);
        ks[(d4 + 0) * PAD + n] = kv.x; ks[(d4 + 1) * PAD + n] = kv.y;
        ks[(d4 + 2) * PAD + n] = kv.z; ks[(d4 + 3) * PAD + n] = kv.w;
        float4 vv = *(const float4*)(vg + off);
        *(float4*)(vsT + n * PAD + d4) = vv;
    }
    __syncthreads();

    float tinv = 1.0f / (temp_p[0] + 1e-6f);
    if (t < 64) {
        float s = 0.f;
        #pragma unroll 8
        for (int n = 0; n < 64; ++n) { float v = qs[t * PAD + n]; s += v * v; }
        cd[t] = 1.0f / fmaxf(sqrtf(s), 1e-12f);
    } else if (t < 128) {
        int r = t - 64;
        float s = 0.f;
        #pragma unroll 8
        for (int n = 0; n < 64; ++n) { float v = ks[r * PAD + n]; s += v * v; }
        knv[r] = 1.0f / fmaxf(sqrtf(s), 1e-12f);
    }
    __syncthreads();
    for (int i = t; i < 64 * 64; i += 256) {
        int d = i >> 6, n = i & 63;
        qs[d * PAD + n] *= cd[d] * knv[d] * tinv;
    }
    __syncthreads();

    u64t sa[4][2];
    #pragma unroll
    for (int i = 0; i < 4; ++i) { sa[i][0] = 0ull; sa[i][1] = 0ull; }
    #pragma unroll 4
    for (int d = 0; d < 64; ++d) {
        float4 av = *(const float4*)(qs + d * PAD + (ty << 2));
        ulonglong2 bv2 = *(const ulonglong2*)(ks + d * PAD + (tx << 2));
        u64t a0 = pk2(av.x, av.x), a1 = pk2(av.y, av.y);
        u64t a2 = pk2(av.z, av.z), a3 = pk2(av.w, av.w);
        sa[0][0] = ffma2(a0, bv2.x, sa[0][0]); sa[0][1] = ffma2(a0, bv2.y, sa[0][1]);
        sa[1][0] = ffma2(a1, bv2.x, sa[1][0]); sa[1][1] = ffma2(a1, bv2.y, sa[1][1]);
        sa[2][0] = ffma2(a2, bv2.x, sa[2][0]); sa[2][1] = ffma2(a2, bv2.y, sa[2][1]);
        sa[3][0] = ffma2(a3, bv2.x, sa[3][0]); sa[3][1] = ffma2(a3, bv2.y, sa[3][1]);
    }

    #pragma unroll
    for (int i = 0; i < 4; ++i) {
        float2 s01 = upk2(sa[i][0]);
        float2 s23 = upk2(sa[i][1]);
        float s0 = s01.x, s1 = s01.y, s2 = s23.x, s3 = s23.y;
        float mx = fmaxf(fmaxf(s0, s1), fmaxf(s2, s3));
        #pragma unroll
        for (int o = 8; o; o >>= 1) mx = fmaxf(mx, __shfl_xor_sync(0xffffffffu, mx, o));
        float e0 = __expf(s0 - mx), e1 = __expf(s1 - mx);
        float e2 = __expf(s2 - mx), e3 = __expf(s3 - mx);
        float sum = e0 + e1 + e2 + e3;
        #pragma unroll
        for (int o = 8; o; o >>= 1) sum += __shfl_xor_sync(0xffffffffu, sum, o);
        float rinv = 1.0f / sum;
        int n = (ty << 2) + i, m0 = tx << 2;
        At[(m0 + 0) * PAD + n] = e0 * rinv;
        At[(m0 + 1) * PAD + n] = e1 * rinv;
        At[(m0 + 2) * PAD + n] = e2 * rinv;
        At[(m0 + 3) * PAD + n] = e3 * rinv;
    }
    __syncthreads();

    u64t oa[4][2];
    #pragma unroll
    for (int i = 0; i < 4; ++i) { oa[i][0] = 0ull; oa[i][1] = 0ull; }
    #pragma unroll 4
    for (int m = 0; m < 64; ++m) {
        float4 av = *(const float4*)(At + m * PAD + (ty << 2));
        ulonglong2 bv2 = *(const ulonglong2*)(vsT + m * PAD + (tx << 2));
        u64t a0 = pk2(av.x, av.x), a1 = pk2(av.y, av.y);
        u64t a2 = pk2(av.z, av.z), a3 = pk2(av.w, av.w);
        oa[0][0] = ffma2(a0, bv2.x, oa[0][0]); oa[0][1] = ffma2(a0, bv2.y, oa[0][1]);
        oa[1][0] = ffma2(a1, bv2.x, oa[1][0]); oa[1][1] = ffma2(a1, bv2.y, oa[1][1]);
        oa[2][0] = ffma2(a2, bv2.x, oa[2][0]); oa[2][1] = ffma2(a2, bv2.y, oa[2][1]);
        oa[3][0] = ffma2(a3, bv2.x, oa[3][0]); oa[3][1] = ffma2(a3, bv2.y, oa[3][1]);
    }
    #pragma unroll
    for (int i = 0; i < 4; ++i) {
        float2 v01 = upk2(oa[i][0]);
        float2 v23 = upk2(oa[i][1]);
        int n = (ty << 2) + i;
        size_t o = (size_t)(b * 64 + n) * 1024 + h * 64 + (tx << 2);
        ushort4 hh, ll;
        hh.x = bf16hi_bits(v01.x); hh.y = bf16hi_bits(v01.y);
        hh.z = bf16hi_bits(v23.x); hh.w = bf16hi_bits(v23.y);
        ll.x = bf16lo_bits(v01.x); ll.y = bf16lo_bits(v01.y);
        ll.z = bf16lo_bits(v23.x); ll.w = bf16lo_bits(v23.y);
        *(ushort4*)(g_ohi + o) = hh;
        *(ushort4*)(g_olo + o) = ll;
    }
}

// ---------------------------------------------------------------------------
// Stats + final LN
// ---------------------------------------------------------------------------
__global__ void __launch_bounds__(256) stats_kernel(
    const float* __restrict__ x, const float* __restrict__ gamma_p)
{
    __shared__ float r1[8], r2[8];
    const int b = blockIdx.x, t = threadIdx.x;
    const float g = gamma_p[0], og = 1.0f - g;
    const float* pb = g_proj + (size_t)b * 65536;
    const float* xb = x + (size_t)b * 65536;
    float s1 = 0.f, s2 = 0.f;
    for (int i = t * 4; i < 65536; i += 1024) {
        float4 p  = *(const float4*)(pb + i);
        float4 xx = *(const float4*)(xb + i);
        float a;
        a = g * p.x + og * xx.x; s1 += a; s2 += a * a;
        a = g * p.y + og * xx.y; s1 += a; s2 += a * a;
        a = g * p.z + og * xx.z; s1 += a; s2 += a * a;
        a = g * p.w + og * xx.w; s1 += a; s2 += a * a;
    }
    #pragma unroll
    for (int o = 16; o; o >>= 1) {
        s1 += __shfl_xor_sync(0xffffffffu, s1, o);
        s2 += __shfl_xor_sync(0xffffffffu, s2, o);
    }
    if ((t & 31) == 0) { r1[t >> 5] = s1; r2[t >> 5] = s2; }
    __syncthreads();
    if (t < 8) {
        s1 = r1[t]; s2 = r2[t];
        #pragma unroll
        for (int o = 4; o; o >>= 1) {
            s1 += __shfl_xor_sync(0x000000ffu, s1, o);
            s2 += __shfl_xor_sync(0x000000ffu, s2, o);
        }
        if (t == 0) {
            float mu  = s1 * (1.0f / 65536.0f);
            float var = s2 * (1.0f / 65536.0f) - mu * mu;
            g_stats[2 * b]     = mu;
            g_stats[2 * b + 1] = rsqrtf(var + 1e-5f);
        }
    }
}

__global__ void __launch_bounds__(256) final_kernel(
    const float* __restrict__ x, const float* __restrict__ gamma_p,
    const float* __restrict__ lnw, const float* __restrict__ lnb,
    float* __restrict__ y)
{
    size_t i4 = (size_t)blockIdx.x * 256 + threadIdx.x;
    int b   = (int)(i4 >> 14);
    int rem = (int)(i4 & 16383);
    size_t base = ((size_t)b << 16) + ((size_t)rem << 2);
    float4 p  = *(const float4*)(g_proj + base);
    float4 xx = *(const float4*)(x + base);
    float4 w  = *(const float4*)(lnw + ((size_t)rem << 2));
    float4 lb = *(const float4*)(lnb + ((size_t)rem << 2));
    float g = gamma_p[0], og = 1.0f - g;
    float mu = g_stats[2 * b], rs = g_stats[2 * b + 1];
    float4 o;
    o.x = (g * p.x + og * xx.x - mu) * rs * w.x + lb.x;
    o.y = (g * p.y + og * xx.y - mu) * rs * w.y + lb.y;
    o.z = (g * p.z + og * xx.z - mu) * rs * w.z + lb.z;
    o.w = (g * p.w + og * xx.w - mu) * rs * w.w + lb.w;
    *(float4*)(y + base) = o;
}

// ---------------------------------------------------------------------------
extern "C" void kernel_launch(void* const* d_in, const int* in_sizes, int n_in,
                              void* d_out, int out_size)
{
    const float* x     = (const float*)d_in[0];
    const float* Wq    = (const float*)d_in[1];
    const float* bq    = (const float*)d_in[2];
    const float* Wk    = (const float*)d_in[3];
    const float* bk    = (const float*)d_in[4];
    const float* Wv    = (const float*)d_in[5];
    const float* bv    = (const float*)d_in[6];
    const float* Wp    = (const float*)d_in[7];
    const float* bp    = (const float*)d_in[8];
    const float* gamma = (const float*)d_in[9];
    const float* temp  = (const float*)d_in[10];
    const float* lnw   = (const float*)d_in[11];
    const float* lnb   = (const float*)d_in[12];
    float* y = (float*)d_out;

    const int sm_att = (4 * 64 * PAD + 128) * (int)sizeof(float);
    cudaFuncSetAttribute(qkv_gemm_kernel, cudaFuncAttributeMaxDynamicSharedMemorySize, SM_GEMM);
    cudaFuncSetAttribute(proj_gemm_kernel, cudaFuncAttributeMaxDynamicSharedMemorySize, SM_GEMM);
    cudaFuncSetAttribute(attn_kernel, cudaFuncAttributeMaxDynamicSharedMemorySize, sm_att);

    prep_w_kernel<<<4096, 256>>>(Wq, Wk, Wv, Wp);
    prep_x_kernel<<<BB, 256>>>(x);
    qkv_gemm_kernel<<<dim3(24, 512), 256, SM_GEMM>>>(bq, bk, bv);
    attn_kernel<<<BB * NH, 256, sm_att>>>(temp);
    proj_gemm_kernel<<<dim3(8, 512), 256, SM_GEMM>>>(bp);
    stats_kernel<<<BB, 256>>>(x, gamma);
    final_kernel<<<65536, 256>>>(x, gamma, lnw, lnb, y);
}